// round 14
// baseline (speedup 1.0000x reference)
#include <cuda_runtime.h>
#include <cuda_fp16.h>
#include <cstdint>
#include <cstddef>

// ---------------- problem constants ----------------
#define B_   64
#define S_   1024
#define E_   300
#define Wn_  1020
#define H0_  512
#define H1_  256
#define H2_  128
#define M_   (B_*Wn_)      // 65280
#define K0P  1536          // layer-0 K (1500) padded to 64

// ---------------- scratch (device globals) ----------------
__device__ __half g_emb[(size_t)(B_*S_+8)*E_];
__device__ __half g_w0[H0_*K0P];
__device__ __half g_w1[H1_*H0_];
__device__ __half g_w2[H2_*H1_];
__device__ __half g_h0[(size_t)M_*H0_];
__device__ float g_pool[B_*H2_];

// ---------------- asm helpers (plain sm_80+ features only) ----------------
__device__ __forceinline__ uint32_t smem_u32(const void* p) {
    uint32_t a;
    asm("{ .reg .u64 t; cvta.to.shared.u64 t, %1; cvt.u32.u64 %0, t; }" : "=r"(a) : "l"(p));
    return a;
}
__device__ __forceinline__ void cpa8(uint32_t s, const void* g) {
    asm volatile("cp.async.ca.shared.global [%0], [%1], 8;" :: "r"(s), "l"(g));
}
__device__ __forceinline__ void cpa16(uint32_t s, const void* g) {
    asm volatile("cp.async.cg.shared.global [%0], [%1], 16;" :: "r"(s), "l"(g));
}
__device__ __forceinline__ void cp_commit() { asm volatile("cp.async.commit_group;"); }
template<int N> __device__ __forceinline__ void cp_wait() {
    asm volatile("cp.async.wait_group %0;" :: "n"(N));
}
__device__ __forceinline__ void ldm_x4(uint32_t a, uint32_t& r0, uint32_t& r1, uint32_t& r2, uint32_t& r3) {
    asm volatile("ldmatrix.sync.aligned.m8n8.x4.shared.b16 {%0,%1,%2,%3}, [%4];"
                 : "=r"(r0), "=r"(r1), "=r"(r2), "=r"(r3) : "r"(a));
}
__device__ __forceinline__ void mma16816(float* c, const uint32_t* a, const uint32_t* b) {
    asm volatile("mma.sync.aligned.m16n8k16.row.col.f32.f16.f16.f32 "
                 "{%0,%1,%2,%3}, {%4,%5,%6,%7}, {%8,%9}, {%0,%1,%2,%3};"
                 : "+f"(c[0]), "+f"(c[1]), "+f"(c[2]), "+f"(c[3])
                 : "r"(a[0]), "r"(a[1]), "r"(a[2]), "r"(a[3]), "r"(b[0]), "r"(b[1]));
}

// ---------------- prep kernels ----------------
__global__ void prep_emb(const int* __restrict__ x, const float* __restrict__ table) {
    int idx = blockIdx.x * 256 + threadIdx.x;
    const int total = (B_ * S_ + 8) * E_;
    if (idx >= total) return;
    int row = idx / E_;
    int e = idx - row * E_;
    float v = 0.f;
    if (row < B_ * S_) {
        int tok = x[row];
        v = table[(size_t)tok * E_ + e];
    }
    g_emb[idx] = __float2half_rn(v);
}

__global__ void prep_weights(const float* __restrict__ W0, const float* __restrict__ W1,
                             const float* __restrict__ W2) {
    int idx = blockIdx.x * 256 + threadIdx.x;
    if (idx < H0_ * K0P) {
        int n = idx / K0P;
        int k = idx - n * K0P;
        float v = (k < 1500) ? W0[(size_t)k * H0_ + n] : 0.f;
        g_w0[idx] = __float2half_rn(v);
        return;
    }
    idx -= H0_ * K0P;
    if (idx < H1_ * H0_) {
        int n = idx / H0_;
        int k = idx - n * H0_;
        g_w1[idx] = __float2half_rn(W1[(size_t)k * H1_ + n]);
        return;
    }
    idx -= H1_ * H0_;
    if (idx < H2_ * H1_) {
        int n = idx / H1_;
        int k = idx - n * H1_;
        g_w2[idx] = __float2half_rn(W2[(size_t)k * H2_ + n]);
        return;
    }
    idx -= H2_ * H1_;
    if (idx < B_ * H2_) g_pool[idx] = 0.f;
}

// ---------------- Layer 0: HMMA GEMM, 4 warps, warp tile 64x64 (R6 exact) ----
__global__ void __launch_bounds__(128, 2)
gemm_l0(const __half* __restrict__ Ag, const __half* __restrict__ Bg,
        const float* __restrict__ bias, __half* __restrict__ Ch)
{
    constexpr int RS   = 40;
    constexpr int PART = 128 * RS;
    constexpr int STG  = 2 * PART;
    constexpr int K    = K0P;
    constexpr int Nn   = H0_;

    extern __shared__ __half sm[];
    const uint32_t smb = smem_u32(sm);

    const int tid  = threadIdx.x;
    const int lane = tid & 31;
    const int wid  = tid >> 5;
    const int wm   = wid & 1;
    const int wn   = wid >> 1;
    const int m0   = blockIdx.x * 128;
    const int n0   = blockIdx.y * 128;
    const int niter = K >> 5;

    // A (window view into emb): 8B chunks, 8/thread
    const __half* aptr[8];
    uint32_t asmoff[8];
#pragma unroll
    for (int t = 0; t < 8; ++t) {
        int idx  = tid + t * 128;
        int row  = idx >> 3;
        int c    = idx & 7;
        int m = m0 + row;
        int b = m / Wn_;
        int w = m - b * Wn_;
        size_t rb = (size_t)(b * S_ + w) * E_;
        aptr[t]   = Ag + rb + c * 4;
        asmoff[t] = row * RS + c * 4;
    }
    const __half* bptr[4];
    uint32_t bsmoff[4];
#pragma unroll
    for (int t = 0; t < 4; ++t) {
        int idx  = tid + t * 128;
        int row  = idx >> 2;
        int c    = idx & 3;
        bptr[t]   = Bg + (size_t)(n0 + row) * K + c * 8;
        bsmoff[t] = PART + row * RS + c * 8;
    }

    auto load_stage = [&](int stage, int k0) {
        uint32_t sb = smb + 2 * (uint32_t)(stage * STG);
#pragma unroll
        for (int t = 0; t < 8; ++t)
            cpa8(sb + 2 * asmoff[t], aptr[t] + k0);
#pragma unroll
        for (int t = 0; t < 4; ++t)
            cpa16(sb + 2 * bsmoff[t], bptr[t] + k0);
        cp_commit();
    };

    const uint32_t a_row  = wm * 64 + (lane & 15);
    const uint32_t a_col  = (lane >> 4) * 8;
    const uint32_t b_row2 = wn * 64 + (lane & 7) + ((lane >> 4) & 1) * 8;
    const uint32_t b_k8   = ((lane >> 3) & 1) * 8;

    float acc[4][8][4];
#pragma unroll
    for (int i = 0; i < 4; ++i)
#pragma unroll
        for (int j = 0; j < 8; ++j)
#pragma unroll
            for (int q = 0; q < 4; ++q) acc[i][j][q] = 0.f;

    load_stage(0, 0);
    load_stage(1, 32);

    for (int it = 0; it < niter; ++it) {
        if (it + 1 < niter) cp_wait<1>(); else cp_wait<0>();
        __syncthreads();
        if (it + 2 < niter) load_stage((it + 2) % 3, (it + 2) * 32);

        const uint32_t sb = smb + 2 * (uint32_t)((it % 3) * STG);
#pragma unroll
        for (int ks = 0; ks < 2; ++ks) {
            uint32_t af[4][4], bf[8][2];
#pragma unroll
            for (int i = 0; i < 4; ++i) {
                uint32_t off = (a_row + i * 16) * RS + (ks * 16 + a_col);
                ldm_x4(sb + 2 * off, af[i][0], af[i][1], af[i][2], af[i][3]);
            }
#pragma unroll
            for (int jj = 0; jj < 4; ++jj) {
                uint32_t off = PART + (b_row2 + jj * 16) * RS + (ks * 16 + b_k8);
                ldm_x4(sb + 2 * off, bf[2*jj][0], bf[2*jj][1], bf[2*jj+1][0], bf[2*jj+1][1]);
            }
#pragma unroll
            for (int i = 0; i < 4; ++i)
#pragma unroll
                for (int j = 0; j < 8; ++j)
                    mma16816(acc[i][j], af[i], bf[j]);
        }
    }

#pragma unroll
    for (int i = 0; i < 4; ++i) {
        const int r0 = m0 + wm * 64 + i * 16 + (lane >> 2);
#pragma unroll
        for (int j = 0; j < 8; ++j) {
            const int c0 = n0 + wn * 64 + j * 8 + (lane & 3) * 2;
            const float bz0 = __ldg(bias + c0), bz1 = __ldg(bias + c0 + 1);
            float v00 = acc[i][j][0] + bz0, v01 = acc[i][j][1] + bz1;
            float v10 = acc[i][j][2] + bz0, v11 = acc[i][j][3] + bz1;
            __half2 hp0, hp1;
            hp0.x = __float2half_rn(v00); hp0.y = __float2half_rn(v01);
            hp1.x = __float2half_rn(v10); hp1.y = __float2half_rn(v11);
            *(__half2*)(Ch + (size_t)r0 * Nn + c0)       = hp0;
            *(__half2*)(Ch + (size_t)(r0 + 8) * Nn + c0) = hp1;
        }
    }
}

// ---------------- Fused layers 1+2 + ragged pooling ----------------
// 256 threads (8 warps 2m x 4n). Phase 1: h1[128x256] = relu(h0*W1+b1) -> smem.
// Phase 2: relu(h1*W2+b2) from smem, masked pool into g_pool.
__global__ void __launch_bounds__(256, 1)
gemm_l12(const __half* __restrict__ h0, const __half* __restrict__ w1,
         const float* __restrict__ b1, const __half* __restrict__ w2,
         const float* __restrict__ b2, const int* __restrict__ lengths)
{
    constexpr int RS  = 40;
    constexpr int PA  = 128 * RS;       // 5120 halfs
    constexpr int PB  = 256 * RS;       // 10240 halfs
    constexpr int STG = PA + PB;        // 15360 halfs
    constexpr int H1OFF = 3 * STG;      // h1 region: 8 ktiles x 128 x 40
    constexpr int K1  = 512;
    constexpr int NIT = K1 / 32;        // 16

    extern __shared__ __half sm[];
    __shared__ float sacc[2][128];
    const uint32_t smb = smem_u32(sm);

    const int tid  = threadIdx.x;
    const int lane = tid & 31;
    const int wid  = tid >> 5;
    const int wm   = wid & 1;           // 0..1 (M, 64 rows)
    const int wn   = wid >> 1;          // 0..3 (N, 64 cols phase1 / 32 cols phase2)
    const int m0   = blockIdx.x * 128;

    if (tid < 128) { sacc[0][tid] = 0.f; sacc[1][tid] = 0.f; }

    // ---- phase-1 load descriptors ----
    // A: 128 rows x 4 x16B = 512 chunks -> 2/thread
    const __half* aptr[2];
    uint32_t asmoff[2];
#pragma unroll
    for (int t = 0; t < 2; ++t) {
        int idx = tid + t * 256;
        int row = idx >> 2;
        int c   = idx & 3;
        aptr[t]   = h0 + (size_t)(m0 + row) * K1 + c * 8;
        asmoff[t] = row * RS + c * 8;
    }
    // B: 256 rows x 4 x16B = 1024 chunks -> 4/thread
    const __half* bptr[4];
    uint32_t bsmoff[4];
#pragma unroll
    for (int t = 0; t < 4; ++t) {
        int idx = tid + t * 256;
        int row = idx >> 2;
        int c   = idx & 3;
        bptr[t]   = w1 + (size_t)row * K1 + c * 8;
        bsmoff[t] = PA + row * RS + c * 8;
    }

    auto load_stage = [&](int stage, int k0) {
        uint32_t sb = smb + 2 * (uint32_t)(stage * STG);
#pragma unroll
        for (int t = 0; t < 2; ++t)
            cpa16(sb + 2 * asmoff[t], aptr[t] + k0);
#pragma unroll
        for (int t = 0; t < 4; ++t)
            cpa16(sb + 2 * bsmoff[t], bptr[t] + k0);
        cp_commit();
    };

    const uint32_t a_row  = wm * 64 + (lane & 15);
    const uint32_t a_col  = (lane >> 4) * 8;
    const uint32_t b_row2 = wn * 64 + (lane & 7) + ((lane >> 4) & 1) * 8;
    const uint32_t b_k8   = ((lane >> 3) & 1) * 8;

    float acc[4][8][4];
#pragma unroll
    for (int i = 0; i < 4; ++i)
#pragma unroll
        for (int j = 0; j < 8; ++j)
#pragma unroll
            for (int q = 0; q < 4; ++q) acc[i][j][q] = 0.f;

    load_stage(0, 0);
    load_stage(1, 32);

    for (int it = 0; it < NIT; ++it) {
        if (it + 1 < NIT) cp_wait<1>(); else cp_wait<0>();
        __syncthreads();
        if (it + 2 < NIT) load_stage((it + 2) % 3, (it + 2) * 32);

        const uint32_t sb = smb + 2 * (uint32_t)((it % 3) * STG);
#pragma unroll
        for (int ks = 0; ks < 2; ++ks) {
            uint32_t af[4][4], bf[8][2];
#pragma unroll
            for (int i = 0; i < 4; ++i) {
                uint32_t off = (a_row + i * 16) * RS + (ks * 16 + a_col);
                ldm_x4(sb + 2 * off, af[i][0], af[i][1], af[i][2], af[i][3]);
            }
#pragma unroll
            for (int jj = 0; jj < 4; ++jj) {
                uint32_t off = PA + (b_row2 + jj * 16) * RS + (ks * 16 + b_k8);
                ldm_x4(sb + 2 * off, bf[2*jj][0], bf[2*jj][1], bf[2*jj+1][0], bf[2*jj+1][1]);
            }
#pragma unroll
            for (int i = 0; i < 4; ++i)
#pragma unroll
                for (int j = 0; j < 8; ++j)
                    mma16816(acc[i][j], af[i], bf[j]);
        }
    }

    // ---- phase-1 epilogue: relu(acc+b1) -> fp16 -> h1 smem ktiles ----
#pragma unroll
    for (int i = 0; i < 4; ++i) {
        const int r0 = wm * 64 + i * 16 + (lane >> 2);  // local row
#pragma unroll
        for (int j = 0; j < 8; ++j) {
            const int c0 = wn * 64 + j * 8 + (lane & 3) * 2;   // 0..254
            const float bz0 = __ldg(b1 + c0), bz1 = __ldg(b1 + c0 + 1);
            float v00 = fmaxf(acc[i][j][0] + bz0, 0.f);
            float v01 = fmaxf(acc[i][j][1] + bz1, 0.f);
            float v10 = fmaxf(acc[i][j][2] + bz0, 0.f);
            float v11 = fmaxf(acc[i][j][3] + bz1, 0.f);
            __half2 hp0, hp1;
            hp0.x = __float2half_rn(v00); hp0.y = __float2half_rn(v01);
            hp1.x = __float2half_rn(v10); hp1.y = __float2half_rn(v11);
            const int kt = c0 >> 5, cc = c0 & 31;
            *(__half2*)(sm + H1OFF + kt * PA + r0 * RS + cc)       = hp0;
            *(__half2*)(sm + H1OFF + kt * PA + (r0 + 8) * RS + cc) = hp1;
        }
    }
    __syncthreads();

    // ---- load W2 into (now free) stage region: layout [8 kt][128 n][40] ----
    {
#pragma unroll
        for (int t = 0; t < 16; ++t) {
            int idx = tid + t * 256;            // 0..4095
            int kt  = idx >> 9;                 // /512
            int rem = idx & 511;
            int row = rem >> 2;
            int c   = rem & 3;
            cpa16(smb + 2 * (uint32_t)(kt * PA + row * RS + c * 8),
                  w2 + (size_t)row * 256 + kt * 32 + c * 8);
        }
        cp_commit();
        cp_wait<0>();
        __syncthreads();
    }

    // ---- phase 2: C2[128x128] = relu(h1 @ W2^T + b2), warp tile 64x32 ----
    float acc2[4][4][4];
#pragma unroll
    for (int i = 0; i < 4; ++i)
#pragma unroll
        for (int j = 0; j < 4; ++j)
#pragma unroll
            for (int q = 0; q < 4; ++q) acc2[i][j][q] = 0.f;

    const uint32_t b2row = wn * 32 + (lane & 7) + ((lane >> 4) & 1) * 8;

#pragma unroll
    for (int kt = 0; kt < 8; ++kt) {
#pragma unroll
        for (int ks = 0; ks < 2; ++ks) {
            uint32_t af[4][4], bf[4][2];
#pragma unroll
            for (int i = 0; i < 4; ++i) {
                uint32_t off = H1OFF + kt * PA + (a_row + i * 16) * RS + (ks * 16 + a_col);
                ldm_x4(smb + 2 * off, af[i][0], af[i][1], af[i][2], af[i][3]);
            }
#pragma unroll
            for (int jj = 0; jj < 2; ++jj) {
                uint32_t off = kt * PA + (b2row + jj * 16) * RS + (ks * 16 + b_k8);
                ldm_x4(smb + 2 * off, bf[2*jj][0], bf[2*jj][1], bf[2*jj+1][0], bf[2*jj+1][1]);
            }
#pragma unroll
            for (int i = 0; i < 4; ++i)
#pragma unroll
                for (int j = 0; j < 4; ++j)
                    mma16816(acc2[i][j], af[i], bf[j]);
        }
    }

    // ---- pooled epilogue ----
    const int b0 = m0 / Wn_;
    const int mbound = (b0 + 1) * Wn_;
    const int v0 = __ldg(lengths + b0) - 4;
    const int v1 = (b0 + 1 < B_) ? (__ldg(lengths + b0 + 1) - 4) : 0;
#pragma unroll
    for (int i = 0; i < 4; ++i) {
        const int rA = m0 + wm * 64 + i * 16 + (lane >> 2);
        const int rB = rA + 8;
        const int sA = (rA >= mbound), sB = (rB >= mbound);
        const int wA = rA - (sA ? mbound : b0 * Wn_);
        const int wB = rB - (sB ? mbound : b0 * Wn_);
        const bool okA = wA < (sA ? v1 : v0);
        const bool okB = wB < (sB ? v1 : v0);
#pragma unroll
        for (int j = 0; j < 4; ++j) {
            const int c0 = wn * 32 + j * 8 + (lane & 3) * 2;
            const float bz0 = __ldg(b2 + c0), bz1 = __ldg(b2 + c0 + 1);
            if (okA) {
                atomicAdd(&sacc[sA][c0],     fmaxf(acc2[i][j][0] + bz0, 0.f));
                atomicAdd(&sacc[sA][c0 + 1], fmaxf(acc2[i][j][1] + bz1, 0.f));
            }
            if (okB) {
                atomicAdd(&sacc[sB][c0],     fmaxf(acc2[i][j][2] + bz0, 0.f));
                atomicAdd(&sacc[sB][c0 + 1], fmaxf(acc2[i][j][3] + bz1, 0.f));
            }
        }
    }
    __syncthreads();
    if (tid < 128) {
        float a0 = sacc[0][tid];
        if (a0 != 0.f) atomicAdd(&g_pool[b0 * H2_ + tid], a0);
        if (mbound < m0 + 128 && b0 + 1 < B_) {
            float a1 = sacc[1][tid];
            if (a1 != 0.f) atomicAdd(&g_pool[(b0 + 1) * H2_ + tid], a1);
        }
    }
}

// ---------------- finalize: divide by valid count ----------------
__global__ void __launch_bounds__(128)
finalize(const int* __restrict__ lengths, float* __restrict__ out) {
    const int b = blockIdx.x, h = threadIdx.x;
    const int valid = lengths[b] - 4;
    out[b * H2_ + h] = g_pool[b * H2_ + h] / (float)valid;
}

// ---------------- launch ----------------
extern "C" void kernel_launch(void* const* d_in, const int* in_sizes, int n_in,
                              void* d_out, int out_size)
{
    const int*   x       = (const int*)  d_in[0];
    const int*   lengths = (const int*)  d_in[1];
    const float* table   = (const float*)d_in[2];
    const float* Wsl     = (const float*)d_in[3];
    const float* bsl     = (const float*)d_in[4];
    const float* W1      = (const float*)d_in[5];
    const float* b1      = (const float*)d_in[6];
    const float* W2      = (const float*)d_in[7];
    const float* b2      = (const float*)d_in[8];
    float*       out     = (float*)d_out;

    __half *embp, *w0p, *w1p, *w2p, *h0p;
    cudaGetSymbolAddress((void**)&embp, g_emb);
    cudaGetSymbolAddress((void**)&w0p, g_w0);
    cudaGetSymbolAddress((void**)&w1p, g_w1);
    cudaGetSymbolAddress((void**)&w2p, g_w2);
    cudaGetSymbolAddress((void**)&h0p, g_h0);

    const int SMEM0  = 3 * (2 * 128 * 40) * 2;               // 61440 B
    const int SMEM12 = (3 * (128 + 256) * 40 + 8 * 128 * 40) * 2;  // 174080 B
    cudaFuncSetAttribute(gemm_l0,  cudaFuncAttributeMaxDynamicSharedMemorySize, SMEM0);
    cudaFuncSetAttribute(gemm_l12, cudaFuncAttributeMaxDynamicSharedMemorySize, SMEM12);

    // prep: embedding gather + fused weights/pool (2 launches)
    {
        int total = (B_ * S_ + 8) * E_;
        prep_emb<<<(total + 255) / 256, 256>>>(x, table);
    }
    {
        int total = H0_ * K0P + H1_ * H0_ + H2_ * H1_ + B_ * H2_;
        prep_weights<<<(total + 255) / 256, 256>>>(Wsl, W1, W2);
    }

    // layer 0: [65280 x 1536] (window view) x [1536 x 512]
    gemm_l0<<<dim3(M_ / 128, H0_ / 128), 128, SMEM0>>>(embp, w0p, bsl, h0p);

    // fused layers 1+2 + ragged pooling
    gemm_l12<<<M_ / 128, 256, SMEM12>>>(h0p, w1p, b1, w2p, b2, lengths);

    // finalize: mean
    finalize<<<B_, 128>>>(lengths, out);
}

// round 15
// speedup vs baseline: 1.5010x; 1.5010x over previous
#include <cuda_runtime.h>
#include <cuda_fp16.h>
#include <cstdint>
#include <cstddef>

// ---------------- problem constants ----------------
#define B_   64
#define S_   1024
#define E_   300
#define Wn_  1020
#define H0_  512
#define H1_  256
#define H2_  128
#define M_   (B_*Wn_)      // 65280
#define K0P  1536          // layer-0 K (1500) padded to 64

// ---------------- scratch (device globals) ----------------
__device__ __half g_emb[(size_t)(B_*S_+8)*E_];
__device__ __half g_w0[H0_*K0P];
__device__ __half g_w1[H1_*H0_];
__device__ __half g_w2[H2_*H1_];
__device__ __half g_h0[(size_t)M_*H0_];
__device__ __half g_h1[(size_t)M_*H1_];
__device__ float g_pool[B_*H2_];

// ---------------- asm helpers (plain sm_80+ features only) ----------------
__device__ __forceinline__ uint32_t smem_u32(const void* p) {
    uint32_t a;
    asm("{ .reg .u64 t; cvta.to.shared.u64 t, %1; cvt.u32.u64 %0, t; }" : "=r"(a) : "l"(p));
    return a;
}
__device__ __forceinline__ void cpa8(uint32_t s, const void* g) {
    asm volatile("cp.async.ca.shared.global [%0], [%1], 8;" :: "r"(s), "l"(g));
}
__device__ __forceinline__ void cpa16(uint32_t s, const void* g) {
    asm volatile("cp.async.cg.shared.global [%0], [%1], 16;" :: "r"(s), "l"(g));
}
__device__ __forceinline__ void cp_commit() { asm volatile("cp.async.commit_group;"); }
template<int N> __device__ __forceinline__ void cp_wait() {
    asm volatile("cp.async.wait_group %0;" :: "n"(N));
}
__device__ __forceinline__ void ldm_x4(uint32_t a, uint32_t& r0, uint32_t& r1, uint32_t& r2, uint32_t& r3) {
    asm volatile("ldmatrix.sync.aligned.m8n8.x4.shared.b16 {%0,%1,%2,%3}, [%4];"
                 : "=r"(r0), "=r"(r1), "=r"(r2), "=r"(r3) : "r"(a));
}
__device__ __forceinline__ void mma16816(float* c, const uint32_t* a, const uint32_t* b) {
    asm volatile("mma.sync.aligned.m16n8k16.row.col.f32.f16.f16.f32 "
                 "{%0,%1,%2,%3}, {%4,%5,%6,%7}, {%8,%9}, {%0,%1,%2,%3};"
                 : "+f"(c[0]), "+f"(c[1]), "+f"(c[2]), "+f"(c[3])
                 : "r"(a[0]), "r"(a[1]), "r"(a[2]), "r"(a[3]), "r"(b[0]), "r"(b[1]));
}

// ---------------- prep kernels ----------------
__global__ void prep_emb(const int* __restrict__ x, const float* __restrict__ table) {
    int idx = blockIdx.x * 256 + threadIdx.x;
    const int total = (B_ * S_ + 8) * E_;
    if (idx >= total) return;
    int row = idx / E_;
    int e = idx - row * E_;
    float v = 0.f;
    if (row < B_ * S_) {
        int tok = x[row];
        v = table[(size_t)tok * E_ + e];
    }
    g_emb[idx] = __float2half_rn(v);
}

// fused weight transpose/convert for all three layers + pool zeroing
__global__ void prep_weights(const float* __restrict__ W0, const float* __restrict__ W1,
                             const float* __restrict__ W2) {
    int idx = blockIdx.x * 256 + threadIdx.x;
    if (idx < H0_ * K0P) {
        int n = idx / K0P;
        int k = idx - n * K0P;
        float v = (k < 1500) ? W0[(size_t)k * H0_ + n] : 0.f;
        g_w0[idx] = __float2half_rn(v);
        return;
    }
    idx -= H0_ * K0P;
    if (idx < H1_ * H0_) {
        int n = idx / H0_;
        int k = idx - n * H0_;
        g_w1[idx] = __float2half_rn(W1[(size_t)k * H1_ + n]);
        return;
    }
    idx -= H1_ * H0_;
    if (idx < H2_ * H1_) {
        int n = idx / H1_;
        int k = idx - n * H1_;
        g_w2[idx] = __float2half_rn(W2[(size_t)k * H2_ + n]);
        return;
    }
    idx -= H2_ * H1_;
    if (idx < B_ * H2_) g_pool[idx] = 0.f;
}

// ---------------- HMMA fp16 GEMM, 4 warps, warp tile 64x64 ----------------
// CTA 128x128, warps 2(m) x 2(n), BK=32, 3 cp.async stages, 1 sync/iter.
// (exact R6 structure — best measured config)
template<bool WIN, bool POOL>
__global__ void __launch_bounds__(128, 2)
gemm_hmma(const __half* __restrict__ Ag, const __half* __restrict__ Bg,
          const float* __restrict__ bias, const int* __restrict__ lengths,
          __half* __restrict__ Ch,
          int K, int Nn, int relu)
{
    constexpr int RS   = 40;            // smem row stride (halfs)
    constexpr int PART = 128 * RS;
    constexpr int STG  = 2 * PART;
    constexpr int NCA  = WIN ? 8 : 4;   // A chunks per thread (8B / 16B)

    extern __shared__ __half sm[];
    __shared__ float sacc[2][128];
    const uint32_t smb = smem_u32(sm);

    const int tid  = threadIdx.x;
    const int lane = tid & 31;
    const int wid  = tid >> 5;
    const int wm   = wid & 1;
    const int wn   = wid >> 1;
    const int m0   = blockIdx.x * 128;
    const int n0   = blockIdx.y * 128;
    const int niter = K >> 5;

    if (POOL && tid < 128) { sacc[0][tid] = 0.f; sacc[1][tid] = 0.f; }

    // ---- A load descriptors ----
    const __half* aptr[NCA];
    uint32_t asmoff[NCA];
    {
        const int CS  = WIN ? 4 : 8;
        const int CPR = 32 / CS;
#pragma unroll
        for (int t = 0; t < NCA; ++t) {
            int idx  = tid + t * 128;
            int row  = idx / CPR;
            int c    = idx - row * CPR;
            size_t rb;
            if (WIN) {
                int m = m0 + row;
                int b = m / Wn_;
                int w = m - b * Wn_;
                rb = (size_t)(b * S_ + w) * E_;
            } else {
                rb = (size_t)(m0 + row) * K;
            }
            aptr[t]   = Ag + rb + c * CS;
            asmoff[t] = row * RS + c * CS;
        }
    }
    // ---- B load descriptors: 128 rows x 4 x16B = 512 -> 4/thread ----
    const __half* bptr[4];
    uint32_t bsmoff[4];
#pragma unroll
    for (int t = 0; t < 4; ++t) {
        int idx  = tid + t * 128;
        int row  = idx >> 2;
        int c    = idx & 3;
        bptr[t]   = Bg + (size_t)(n0 + row) * K + c * 8;
        bsmoff[t] = PART + row * RS + c * 8;
    }

    auto load_stage = [&](int stage, int k0) {
        uint32_t sb = smb + 2 * (uint32_t)(stage * STG);
#pragma unroll
        for (int t = 0; t < NCA; ++t) {
            if (WIN) cpa8(sb + 2 * asmoff[t], aptr[t] + k0);
            else     cpa16(sb + 2 * asmoff[t], aptr[t] + k0);
        }
#pragma unroll
        for (int t = 0; t < 4; ++t)
            cpa16(sb + 2 * bsmoff[t], bptr[t] + k0);
        cp_commit();
    };

    // fragment addressing
    const uint32_t a_row  = wm * 64 + (lane & 15);
    const uint32_t a_col  = (lane >> 4) * 8;
    const uint32_t b_row2 = wn * 64 + (lane & 7) + ((lane >> 4) & 1) * 8;
    const uint32_t b_k8   = ((lane >> 3) & 1) * 8;

    float acc[4][8][4];
#pragma unroll
    for (int i = 0; i < 4; ++i)
#pragma unroll
        for (int j = 0; j < 8; ++j)
#pragma unroll
            for (int q = 0; q < 4; ++q) acc[i][j][q] = 0.f;

    load_stage(0, 0);
    load_stage(1, 32);

    for (int it = 0; it < niter; ++it) {
        if (it + 1 < niter) cp_wait<1>(); else cp_wait<0>();
        __syncthreads();
        if (it + 2 < niter) load_stage((it + 2) % 3, (it + 2) * 32);

        const uint32_t sb = smb + 2 * (uint32_t)((it % 3) * STG);
#pragma unroll
        for (int ks = 0; ks < 2; ++ks) {
            uint32_t af[4][4], bf[8][2];
#pragma unroll
            for (int i = 0; i < 4; ++i) {
                uint32_t off = (a_row + i * 16) * RS + (ks * 16 + a_col);
                ldm_x4(sb + 2 * off, af[i][0], af[i][1], af[i][2], af[i][3]);
            }
#pragma unroll
            for (int jj = 0; jj < 4; ++jj) {
                uint32_t off = PART + (b_row2 + jj * 16) * RS + (ks * 16 + b_k8);
                ldm_x4(sb + 2 * off, bf[2*jj][0], bf[2*jj][1], bf[2*jj+1][0], bf[2*jj+1][1]);
            }
#pragma unroll
            for (int i = 0; i < 4; ++i)
#pragma unroll
                for (int j = 0; j < 8; ++j)
                    mma16816(acc[i][j], af[i], bf[j]);
        }
    }

    // ---- epilogue ----
    if (POOL) {
        const int b0 = m0 / Wn_;
        const int mbound = (b0 + 1) * Wn_;
        const int v0 = __ldg(lengths + b0) - 4;
        const int v1 = (b0 + 1 < B_) ? (__ldg(lengths + b0 + 1) - 4) : 0;
#pragma unroll
        for (int i = 0; i < 4; ++i) {
            const int rA = m0 + wm * 64 + i * 16 + (lane >> 2);
            const int rB = rA + 8;
            const int sA = (rA >= mbound), sB = (rB >= mbound);
            const int wA = rA - (sA ? mbound : b0 * Wn_);
            const int wB = rB - (sB ? mbound : b0 * Wn_);
            const bool okA = wA < (sA ? v1 : v0);
            const bool okB = wB < (sB ? v1 : v0);
#pragma unroll
            for (int j = 0; j < 8; ++j) {
                const int c0 = wn * 64 + j * 8 + (lane & 3) * 2;
                const float bz0 = __ldg(bias + c0), bz1 = __ldg(bias + c0 + 1);
                if (okA) {
                    atomicAdd(&sacc[sA][c0],     fmaxf(acc[i][j][0] + bz0, 0.f));
                    atomicAdd(&sacc[sA][c0 + 1], fmaxf(acc[i][j][1] + bz1, 0.f));
                }
                if (okB) {
                    atomicAdd(&sacc[sB][c0],     fmaxf(acc[i][j][2] + bz0, 0.f));
                    atomicAdd(&sacc[sB][c0 + 1], fmaxf(acc[i][j][3] + bz1, 0.f));
                }
            }
        }
        __syncthreads();
        if (tid < 128) {
            float a0 = sacc[0][tid];
            if (a0 != 0.f) atomicAdd(&g_pool[b0 * H2_ + tid], a0);
            if (mbound < m0 + 128 && b0 + 1 < B_) {
                float a1 = sacc[1][tid];
                if (a1 != 0.f) atomicAdd(&g_pool[(b0 + 1) * H2_ + tid], a1);
            }
        }
    } else {
#pragma unroll
        for (int i = 0; i < 4; ++i) {
            const int r0 = m0 + wm * 64 + i * 16 + (lane >> 2);
#pragma unroll
            for (int j = 0; j < 8; ++j) {
                const int c0 = n0 + wn * 64 + j * 8 + (lane & 3) * 2;
                const float bz0 = __ldg(bias + c0), bz1 = __ldg(bias + c0 + 1);
                float v00 = acc[i][j][0] + bz0, v01 = acc[i][j][1] + bz1;
                float v10 = acc[i][j][2] + bz0, v11 = acc[i][j][3] + bz1;
                if (relu) {
                    v00 = fmaxf(v00, 0.f); v01 = fmaxf(v01, 0.f);
                    v10 = fmaxf(v10, 0.f); v11 = fmaxf(v11, 0.f);
                }
                __half2 hp0, hp1;
                hp0.x = __float2half_rn(v00); hp0.y = __float2half_rn(v01);
                hp1.x = __float2half_rn(v10); hp1.y = __float2half_rn(v11);
                *(__half2*)(Ch + (size_t)r0 * Nn + c0)       = hp0;
                *(__half2*)(Ch + (size_t)(r0 + 8) * Nn + c0) = hp1;
            }
        }
    }
}

// ---------------- finalize: divide by valid count ----------------
__global__ void __launch_bounds__(128)
finalize(const int* __restrict__ lengths, float* __restrict__ out) {
    const int b = blockIdx.x, h = threadIdx.x;
    const int valid = lengths[b] - 4;
    out[b * H2_ + h] = g_pool[b * H2_ + h] / (float)valid;
}

// ---------------- launch ----------------
extern "C" void kernel_launch(void* const* d_in, const int* in_sizes, int n_in,
                              void* d_out, int out_size)
{
    const int*   x       = (const int*)  d_in[0];
    const int*   lengths = (const int*)  d_in[1];
    const float* table   = (const float*)d_in[2];
    const float* Wsl     = (const float*)d_in[3];
    const float* bsl     = (const float*)d_in[4];
    const float* W1      = (const float*)d_in[5];
    const float* b1      = (const float*)d_in[6];
    const float* W2      = (const float*)d_in[7];
    const float* b2      = (const float*)d_in[8];
    float*       out     = (float*)d_out;

    __half *embp, *w0p, *w1p, *w2p, *h0p, *h1p;
    cudaGetSymbolAddress((void**)&embp, g_emb);
    cudaGetSymbolAddress((void**)&w0p, g_w0);
    cudaGetSymbolAddress((void**)&w1p, g_w1);
    cudaGetSymbolAddress((void**)&w2p, g_w2);
    cudaGetSymbolAddress((void**)&h0p, g_h0);
    cudaGetSymbolAddress((void**)&h1p, g_h1);

    const int SMEM = 3 * (2 * 128 * 40) * 2;   // 61440 B per CTA, 2 CTAs/SM
    cudaFuncSetAttribute((void*)gemm_hmma<true,  false>, cudaFuncAttributeMaxDynamicSharedMemorySize, SMEM);
    cudaFuncSetAttribute((void*)gemm_hmma<false, false>, cudaFuncAttributeMaxDynamicSharedMemorySize, SMEM);
    cudaFuncSetAttribute((void*)gemm_hmma<false, true>,  cudaFuncAttributeMaxDynamicSharedMemorySize, SMEM);

    // prep: embedding gather + fused weights/pool (2 launches)
    {
        int total = (B_ * S_ + 8) * E_;
        prep_emb<<<(total + 255) / 256, 256>>>(x, table);
    }
    {
        int total = H0_ * K0P + H1_ * H0_ + H2_ * H1_ + B_ * H2_;
        prep_weights<<<(total + 255) / 256, 256>>>(Wsl, W1, W2);
    }

    // layer 0: [65280 x 1536] (window view) x [1536 x 512]
    gemm_hmma<true, false><<<dim3(M_ / 128, H0_ / 128), 128, SMEM>>>(
        embp, w0p, bsl, nullptr, h0p, K0P, H0_, 0);
    // layer 1: relu([65280 x 512] x [512 x 256])
    gemm_hmma<false, false><<<dim3(M_ / 128, H1_ / 128), 128, SMEM>>>(
        h0p, w1p, b1, nullptr, h1p, H0_, H1_, 1);
    // layer 2: relu([65280 x 256] x [256 x 128]) fused with ragged pooling
    gemm_hmma<false, true><<<dim3(M_ / 128, 1), 128, SMEM>>>(
        h1p, w2p, b2, lengths, nullptr, H1_, H2_, 1);

    // finalize: mean
    finalize<<<B_, 128>>>(lengths, out);
}